// round 1
// baseline (speedup 1.0000x reference)
#include <cuda_runtime.h>

#define N_TOK 2048
#define D_IN  1024
#define D_ATT 1024
#define NHEAD 8
#define D_HEAD 128
#define D_V    64
#define NN ((long long)N_TOK * N_TOK)

// ---------------- scratch (static device memory; no allocations) ----------------
__device__ float g_Q1[N_TOK * D_ATT];
__device__ float g_K1[N_TOK * D_ATT];
__device__ float g_Q2[N_TOK * D_ATT];
__device__ float g_K2[N_TOK * D_ATT];
__device__ float g_V1[N_TOK * 512];
__device__ float g_V2[N_TOK * 512];
__device__ float g_S1[(long long)NHEAD * N_TOK * N_TOK];
__device__ float g_S2[(long long)NHEAD * N_TOK * N_TOK];
__device__ float g_M1[(long long)N_TOK * N_TOK];
__device__ float g_M2[(long long)N_TOK * N_TOK];

// ---------------- generic SGEMM body (inlined into each stage kernel) ----------------
// C[bm:bm+BM, bn:bn+BN] = alpha * A @ (TRB ? B^T : B) (+ bias)
// A: M x K (lda), B: K x N (ldb) or N x K if TRB, C: ldc. All tiles exactly divide.
template <int BM, int BN, int BK, int TM, int TN, bool TRB, bool BIAS>
__device__ __forceinline__ void gemm_body(
    const float* __restrict__ A, int lda,
    const float* __restrict__ B, int ldb,
    float* __restrict__ C, int ldc,
    int K, int bm, int bn,
    const float* __restrict__ bias, float alpha)
{
    constexpr int THREADS = (BM / TM) * (BN / TN);
    __shared__ float As[BK][BM];
    __shared__ float Bs[BK][BN];

    const int tid = threadIdx.x;
    const int tx = tid % (BN / TN);
    const int ty = tid / (BN / TN);

    float acc[TM][TN];
#pragma unroll
    for (int i = 0; i < TM; i++)
#pragma unroll
        for (int j = 0; j < TN; j++) acc[i][j] = 0.f;

    for (int k0 = 0; k0 < K; k0 += BK) {
        // load A tile (BM x BK), store transposed As[k][m]
#pragma unroll
        for (int idx = tid * 4; idx < BM * BK; idx += THREADS * 4) {
            int m = idx / BK;
            int kk = idx % BK;
            float4 v = *(const float4*)(A + (long long)(bm + m) * lda + k0 + kk);
            As[kk + 0][m] = v.x; As[kk + 1][m] = v.y;
            As[kk + 2][m] = v.z; As[kk + 3][m] = v.w;
        }
        if (TRB) {
            // B is N x K row-major; Bs[k][n] = B[bn+n][k0+k]
#pragma unroll
            for (int idx = tid * 4; idx < BK * BN; idx += THREADS * 4) {
                int n = idx / BK;
                int kk = idx % BK;
                float4 v = *(const float4*)(B + (long long)(bn + n) * ldb + k0 + kk);
                Bs[kk + 0][n] = v.x; Bs[kk + 1][n] = v.y;
                Bs[kk + 2][n] = v.z; Bs[kk + 3][n] = v.w;
            }
        } else {
#pragma unroll
            for (int idx = tid * 4; idx < BK * BN; idx += THREADS * 4) {
                int kk = idx / BN;
                int n = idx % BN;
                *(float4*)&Bs[kk][n] =
                    *(const float4*)(B + (long long)(k0 + kk) * ldb + bn + n);
            }
        }
        __syncthreads();

#pragma unroll
        for (int kk = 0; kk < BK; kk++) {
            float ra[TM], rb[TN];
#pragma unroll
            for (int i = 0; i < TM; i += 4)
                *(float4*)&ra[i] = *(const float4*)&As[kk][ty * TM + i];
#pragma unroll
            for (int j = 0; j < TN; j += 4)
                *(float4*)&rb[j] = *(const float4*)&Bs[kk][tx * TN + j];
#pragma unroll
            for (int i = 0; i < TM; i++)
#pragma unroll
                for (int j = 0; j < TN; j++)
                    acc[i][j] = fmaf(ra[i], rb[j], acc[i][j]);
        }
        __syncthreads();
    }

#pragma unroll
    for (int i = 0; i < TM; i++) {
        long long row = bm + ty * TM + i;
#pragma unroll
        for (int j = 0; j < TN; j += 4) {
            int col = bn + tx * TN + j;
            float4 r;
            r.x = acc[i][j + 0] * alpha;
            r.y = acc[i][j + 1] * alpha;
            r.z = acc[i][j + 2] * alpha;
            r.w = acc[i][j + 3] * alpha;
            if (BIAS) {
                r.x += bias[col + 0]; r.y += bias[col + 1];
                r.z += bias[col + 2]; r.w += bias[col + 3];
            }
            *(float4*)(C + row * ldc + col) = r;
        }
    }
}

// ---------------- stage 0: mask transpose m[n][m] = (g[m][n]-1)*1e4 ----------------
__global__ void mask_transpose_kernel(const float* __restrict__ G1,
                                      const float* __restrict__ G2,
                                      float* __restrict__ M1,
                                      float* __restrict__ M2)
{
    __shared__ float t1[32][33];
    __shared__ float t2[32][33];
    int bx = blockIdx.x * 32;
    int by = blockIdx.y * 32;
    int x = bx + threadIdx.x;
#pragma unroll
    for (int i = threadIdx.y; i < 32; i += 8) {
        t1[i][threadIdx.x] = G1[(long long)(by + i) * N_TOK + x];
        t2[i][threadIdx.x] = G2[(long long)(by + i) * N_TOK + x];
    }
    __syncthreads();
    int ox = by + threadIdx.x;
#pragma unroll
    for (int i = threadIdx.y; i < 32; i += 8) {
        M1[(long long)(bx + i) * N_TOK + ox] = (t1[threadIdx.x][i] - 1.f) * 10000.f;
        M2[(long long)(bx + i) * N_TOK + ox] = (t2[threadIdx.x][i] - 1.f) * 10000.f;
    }
}

// ---------------- stage 1: all 6 projections in one launch ----------------
// column-blocks: 0-7 Wq1->Q1, 8-15 Wk1->K1, 16-23 Wq2->Q2, 24-31 Wk2->K2,
//                32-35 Wv1->V1, 36-39 Wv2->V2
__global__ __launch_bounds__(256)
void proj_kernel(const float* __restrict__ x,
                 const float* __restrict__ Wq1, const float* __restrict__ bq1,
                 const float* __restrict__ Wk1, const float* __restrict__ bk1,
                 const float* __restrict__ Wv1, const float* __restrict__ bv1,
                 const float* __restrict__ Wq2, const float* __restrict__ bq2,
                 const float* __restrict__ Wk2, const float* __restrict__ bk2,
                 const float* __restrict__ Wv2, const float* __restrict__ bv2)
{
    int cb = blockIdx.x;
    int bm = blockIdx.y * 128;
    const float* W; const float* bias; float* Cout; int ld; int bn;
    if (cb < 32) {
        int r = cb >> 3;
        bn = (cb & 7) * 128;
        ld = 1024;
        if (r == 0)      { W = Wq1; bias = bq1; Cout = g_Q1; }
        else if (r == 1) { W = Wk1; bias = bk1; Cout = g_K1; }
        else if (r == 2) { W = Wq2; bias = bq2; Cout = g_Q2; }
        else             { W = Wk2; bias = bk2; Cout = g_K2; }
    } else {
        int r = (cb - 32) >> 2;
        bn = ((cb - 32) & 3) * 128;
        ld = 512;
        if (r == 0) { W = Wv1; bias = bv1; Cout = g_V1; }
        else        { W = Wv2; bias = bv2; Cout = g_V2; }
    }
    gemm_body<128, 128, 8, 8, 8, false, true>(
        x, D_IN, W, ld, Cout, ld, D_IN, bm, bn, bias, 1.f);
}

// ---------------- stage 2: scores S = scale * Q K^T (batched over {s1,s2} x head) ----------------
__global__ __launch_bounds__(256)
void score_kernel(float scale)
{
    int z = blockIdx.z;           // 0..15
    int mat = z >> 3;
    int h = z & 7;
    const float* A = (mat ? g_Q2 : g_Q1) + h * D_HEAD;
    const float* B = (mat ? g_K2 : g_K1) + h * D_HEAD;
    float* C = (mat ? g_S2 : g_S1) + (long long)h * NN;
    gemm_body<128, 128, 8, 8, 8, true, false>(
        A, D_ATT, B, D_ATT, C, N_TOK, D_HEAD,
        blockIdx.y * 128, blockIdx.x * 128, nullptr, scale);
}

// ---------------- stage 3: dual gathered softmax (in place over S1/S2) ----------------
__device__ __forceinline__ float warpRedMax(float v) {
#pragma unroll
    for (int o = 16; o > 0; o >>= 1) v = fmaxf(v, __shfl_xor_sync(0xffffffffu, v, o));
    return v;
}
__device__ __forceinline__ float warpRedSum(float v) {
#pragma unroll
    for (int o = 16; o > 0; o >>= 1) v += __shfl_xor_sync(0xffffffffu, v, o);
    return v;
}

__global__ __launch_bounds__(256)
void softmax_gather_kernel(float* __restrict__ S1, float* __restrict__ S2,
                           const int* __restrict__ n2c, const int* __restrict__ c2n,
                           const float* __restrict__ M1, const float* __restrict__ M2)
{
    const int n = blockIdx.x;
    const int h = blockIdx.y;
    float* s1row = S1 + ((long long)h * N_TOK + n) * N_TOK;
    float* s2row = S2 + ((long long)h * N_TOK + n) * N_TOK;
    __shared__ float sh1[N_TOK];
    __shared__ float sh2[N_TOK];
    __shared__ float red[32];
    const int tid = threadIdx.x;
    const int lane = tid & 31, wid = tid >> 5;

#pragma unroll
    for (int i = 0; i < 8; i++) {
        int m = tid + i * 256;
        sh1[m] = s1row[m];
        sh2[m] = s2row[m];
    }
    __syncthreads();

    const int* c2nrow = c2n + (long long)n * N_TOK;
    const int* n2crow = n2c + (long long)n * N_TOK;
    const float* m1row = M1 + (long long)n * N_TOK;
    const float* m2row = M2 + (long long)n * N_TOK;

    float z1[8], z2[8];
    float mx1 = -1e30f, mx2 = -1e30f;
#pragma unroll
    for (int i = 0; i < 8; i++) {
        int m = tid + i * 256;
        z1[i] = sh1[m] + sh2[c2nrow[m]] + m1row[m];
        z2[i] = sh2[m] + sh1[n2crow[m]] + m2row[m];
        mx1 = fmaxf(mx1, z1[i]);
        mx2 = fmaxf(mx2, z2[i]);
    }
    mx1 = warpRedMax(mx1);
    mx2 = warpRedMax(mx2);
    if (lane == 0) { red[wid] = mx1; red[wid + 8] = mx2; }
    __syncthreads();
    if (wid == 0) {
        float a = (lane < 8) ? red[lane] : -1e30f;
        float b = (lane < 8) ? red[lane + 8] : -1e30f;
        a = warpRedMax(a);
        b = warpRedMax(b);
        if (lane == 0) { red[16] = a; red[17] = b; }
    }
    __syncthreads();
    mx1 = red[16];
    mx2 = red[17];

    float sum1 = 0.f, sum2 = 0.f;
#pragma unroll
    for (int i = 0; i < 8; i++) {
        z1[i] = __expf(z1[i] - mx1);
        z2[i] = __expf(z2[i] - mx2);
        sum1 += z1[i];
        sum2 += z2[i];
    }
    sum1 = warpRedSum(sum1);
    sum2 = warpRedSum(sum2);
    __syncthreads();
    if (lane == 0) { red[wid] = sum1; red[wid + 8] = sum2; }
    __syncthreads();
    if (wid == 0) {
        float a = (lane < 8) ? red[lane] : 0.f;
        float b = (lane < 8) ? red[lane + 8] : 0.f;
        a = warpRedSum(a);
        b = warpRedSum(b);
        if (lane == 0) { red[16] = a; red[17] = b; }
    }
    __syncthreads();
    float inv1 = 1.f / red[16];
    float inv2 = 1.f / red[17];
#pragma unroll
    for (int i = 0; i < 8; i++) {
        int m = tid + i * 256;
        s1row[m] = z1[i] * inv1;
        s2row[m] = z2[i] * inv2;
    }
}

// ---------------- stage 4: out = concat(A1 @ V1, A2 @ V2), batched over {1,2} x head ----------------
__global__ __launch_bounds__(256)
void av_kernel(float* __restrict__ out)
{
    int z = blockIdx.z;          // 0..15
    int mat = z >> 3;
    int h = z & 7;
    const float* A = (mat ? g_S2 : g_S1) + (long long)h * NN;
    const float* B = (mat ? g_V2 : g_V1) + h * D_V;
    float* C = out + mat * 512 + h * D_V;
    gemm_body<128, 64, 8, 8, 4, false, false>(
        A, N_TOK, B, 512, C, 1024, N_TOK,
        blockIdx.y * 128, 0, nullptr, 1.f);
}

// ---------------- launch ----------------
extern "C" void kernel_launch(void* const* d_in, const int* in_sizes, int n_in,
                              void* d_out, int out_size)
{
    const float* x   = (const float*)d_in[0];
    const float* fst = (const float*)d_in[1];
    const float* sec = (const float*)d_in[2];
    const int*   n2c = (const int*)d_in[3];
    const int*   c2n = (const int*)d_in[4];
    const float* Wq1 = (const float*)d_in[5];
    const float* bq1 = (const float*)d_in[6];
    const float* Wk1 = (const float*)d_in[7];
    const float* bk1 = (const float*)d_in[8];
    const float* Wv1 = (const float*)d_in[9];
    const float* bv1 = (const float*)d_in[10];
    const float* Wq2 = (const float*)d_in[11];
    const float* bq2 = (const float*)d_in[12];
    const float* Wk2 = (const float*)d_in[13];
    const float* bk2 = (const float*)d_in[14];
    const float* Wv2 = (const float*)d_in[15];
    const float* bv2 = (const float*)d_in[16];
    float* out = (float*)d_out;

    float *S1, *S2, *M1, *M2;
    cudaGetSymbolAddress((void**)&S1, g_S1);
    cudaGetSymbolAddress((void**)&S2, g_S2);
    cudaGetSymbolAddress((void**)&M1, g_M1);
    cudaGetSymbolAddress((void**)&M2, g_M2);

    // stage 0: transposed masks
    mask_transpose_kernel<<<dim3(64, 64), dim3(32, 8)>>>(fst, sec, M1, M2);

    // stage 1: all six projections (640 blocks)
    proj_kernel<<<dim3(40, 16), 256>>>(x, Wq1, bq1, Wk1, bk1, Wv1, bv1,
                                       Wq2, bq2, Wk2, bk2, Wv2, bv2);

    // stage 2: scores (4096 blocks)
    const float scale = 0.08838834764831845f;  // 1/sqrt(128)
    score_kernel<<<dim3(16, 16, 16), 256>>>(scale);

    // stage 3: gathered dual softmax (16384 blocks)
    softmax_gather_kernel<<<dim3(2048, 8), 256>>>(S1, S2, n2c, c2n, M1, M2);

    // stage 4: AV + concat (256 blocks)
    av_kernel<<<dim3(1, 16, 16), 256>>>(out);
}

// round 3
// speedup vs baseline: 2.0299x; 2.0299x over previous
#include <cuda_runtime.h>
#include <cuda_bf16.h>
#include <cstdint>

#define N_TOK 2048
#define NN (8LL * 2048 * 2048)

typedef __nv_bfloat16 bf16;

__device__ __forceinline__ uint32_t smem_to_u32(const void* p) {
    uint32_t a;
    asm("{ .reg .u64 t; cvta.to.shared.u64 t, %1; cvt.u32.u64 %0, t; }" : "=r"(a) : "l"(p));
    return a;
}

__device__ __forceinline__ void ldmatrix_x4(uint32_t& r0, uint32_t& r1, uint32_t& r2,
                                            uint32_t& r3, uint32_t addr) {
    asm volatile("ldmatrix.sync.aligned.m8n8.x4.shared.b16 {%0,%1,%2,%3}, [%4];"
                 : "=r"(r0), "=r"(r1), "=r"(r2), "=r"(r3) : "r"(addr));
}

__device__ __forceinline__ void mma16816(float c[4], const uint32_t a[4], const uint32_t b[2]) {
    asm volatile(
        "mma.sync.aligned.m16n8k16.row.col.f32.bf16.bf16.f32 "
        "{%0,%1,%2,%3}, {%4,%5,%6,%7}, {%8,%9}, {%0,%1,%2,%3};"
        : "+f"(c[0]), "+f"(c[1]), "+f"(c[2]), "+f"(c[3])
        : "r"(a[0]), "r"(a[1]), "r"(a[2]), "r"(a[3]), "r"(b[0]), "r"(b[1]));
}

// ============================ device scratch ============================
__device__ __align__(16) bf16 g_Xh[2048 * 1024];
__device__ __align__(16) bf16 g_Xl[2048 * 1024];
__device__ __align__(16) bf16 g_WTh[5242880];   // q1,k1,q2,k2 (1M each) + v1,v2 (512K each), [N,K]
__device__ __align__(16) bf16 g_WTl[5242880];
__device__ __align__(16) bf16 g_QKh[4][2048 * 1024];  // 0:q1 1:k1 2:q2 3:k2
__device__ __align__(16) bf16 g_QKl[4][2048 * 1024];
__device__ __align__(16) bf16 g_VTh[1024 * 2048];     // rows: mat*512 + vcol, cols: token
__device__ __align__(16) bf16 g_VTl[1024 * 2048];
__device__ __align__(16) float g_S1[NN];   // fp32 scores; after softmax: [hi bf16 x2048 | lo bf16 x2048] per row
__device__ __align__(16) float g_S2[NN];
__device__ float g_M1[2048LL * 2048];
__device__ float g_M2[2048LL * 2048];

// ============================ conversion kernels ============================
__global__ __launch_bounds__(256) void convx_kernel(const float* __restrict__ x) {
    int i = (blockIdx.x * 256 + threadIdx.x) * 4;
    float4 v = *(const float4*)(x + i);
    float vv[4] = {v.x, v.y, v.z, v.w};
    bf16 h[4], l[4];
#pragma unroll
    for (int j = 0; j < 4; j++) {
        h[j] = __float2bfloat16(vv[j]);
        l[j] = __float2bfloat16(vv[j] - __bfloat162float(h[j]));
    }
    *(uint2*)&g_Xh[i] = *(uint2*)h;
    *(uint2*)&g_Xl[i] = *(uint2*)l;
}

__global__ __launch_bounds__(256)
void convw_kernel(const float* __restrict__ w0, const float* __restrict__ w1,
                  const float* __restrict__ w2, const float* __restrict__ w3,
                  const float* __restrict__ w4, const float* __restrict__ w5) {
    int z = blockIdx.z;
    const float* W;
    int Ncols;
    long long base;
    switch (z) {
        case 0: W = w0; Ncols = 1024; base = 0; break;
        case 1: W = w1; Ncols = 1024; base = 1048576; break;
        case 2: W = w2; Ncols = 1024; base = 2097152; break;
        case 3: W = w3; Ncols = 1024; base = 3145728; break;
        case 4: W = w4; Ncols = 512;  base = 4194304; break;
        default:W = w5; Ncols = 512;  base = 4718592; break;
    }
    int bn = blockIdx.x * 32, bk = blockIdx.y * 32;
    if (bn >= Ncols) return;
    __shared__ float t[32][33];
#pragma unroll
    for (int i = threadIdx.y; i < 32; i += 8)
        t[i][threadIdx.x] = W[(long long)(bk + i) * Ncols + bn + threadIdx.x];
    __syncthreads();
#pragma unroll
    for (int i = threadIdx.y; i < 32; i += 8) {
        float v = t[threadIdx.x][i];
        bf16 hh = __float2bfloat16(v);
        long long o = base + (long long)(bn + i) * 1024 + bk + threadIdx.x;
        g_WTh[o] = hh;
        g_WTl[o] = __float2bfloat16(v - __bfloat162float(hh));
    }
}

__global__ void mask_transpose_kernel(const float* __restrict__ G1,
                                      const float* __restrict__ G2) {
    __shared__ float t1[32][33];
    __shared__ float t2[32][33];
    int bx = blockIdx.x * 32;
    int by = blockIdx.y * 32;
    int x = bx + threadIdx.x;
#pragma unroll
    for (int i = threadIdx.y; i < 32; i += 8) {
        t1[i][threadIdx.x] = G1[(long long)(by + i) * N_TOK + x];
        t2[i][threadIdx.x] = G2[(long long)(by + i) * N_TOK + x];
    }
    __syncthreads();
    int ox = by + threadIdx.x;
#pragma unroll
    for (int i = threadIdx.y; i < 32; i += 8) {
        g_M1[(long long)(bx + i) * N_TOK + ox] = (t1[threadIdx.x][i] - 1.f) * 10000.f;
        g_M2[(long long)(bx + i) * N_TOK + ox] = (t2[threadIdx.x][i] - 1.f) * 10000.f;
    }
}

// ============================ mma.sync GEMM body ============================
// acc[MI][4][4] += A(128,K) * B(BN,K)^T in 3-term bf16 split.
// A row-major [m][k] (lda), B row-major [n][k] (ldb). 256 threads, K % 32 == 0.
// Warp grid: WM x WN (WM*WN == 8). Warp tile: (MI*16) x 32.
// smem rows padded to 40 bf16 (80B) -> ldmatrix conflict-free.
template <int BN, int WM, int WN>
__device__ __forceinline__ void gemm_mma(
    const bf16* __restrict__ aH, const bf16* __restrict__ aL, int lda,
    const bf16* __restrict__ bH, const bf16* __restrict__ bL, int ldb,
    int K, float acc[128 / (WM * 16)][4][4])
{
    constexpr int MI = 128 / (WM * 16);
    __shared__ __align__(16) bf16 sAh[128 * 40];
    __shared__ __align__(16) bf16 sAl[128 * 40];
    __shared__ __align__(16) bf16 sBh[BN * 40];
    __shared__ __align__(16) bf16 sBl[BN * 40];
    const int tid = threadIdx.x;
    const int wid = tid >> 5, lane = tid & 31;
    const int wm = (wid / WN) * (MI * 16);
    const int wn = (wid % WN) * 32;
    const uint32_t sAh_b = smem_to_u32(sAh), sAl_b = smem_to_u32(sAl);
    const uint32_t sBh_b = smem_to_u32(sBh), sBl_b = smem_to_u32(sBl);

    // ldmatrix per-lane address offsets (bf16 units within padded tile)
    const int a_row = wm + (lane & 7) + ((lane >> 3) & 1) * 8;
    const int a_cofs = (lane >> 4) * 8;
    const int b_row = wn + (lane & 7) + ((lane >> 4) & 1) * 8;
    const int b_cofs = ((lane >> 3) & 1) * 8;

    for (int k0 = 0; k0 < K; k0 += 32) {
        // stage A tiles (128 x 32)
#pragma unroll
        for (int i = 0; i < 2; i++) {
            int idx = i * 256 + tid;
            int r = idx >> 2, c = (idx & 3) * 8;
            long long g = (long long)r * lda + k0 + c;
            *(uint4*)&sAh[r * 40 + c] = *(const uint4*)(aH + g);
            *(uint4*)&sAl[r * 40 + c] = *(const uint4*)(aL + g);
        }
        // stage B tiles (BN x 32)
#pragma unroll
        for (int i = 0; i < BN / 64; i++) {
            int idx = i * 256 + tid;
            int r = idx >> 2, c = (idx & 3) * 8;
            long long g = (long long)r * ldb + k0 + c;
            *(uint4*)&sBh[r * 40 + c] = *(const uint4*)(bH + g);
            *(uint4*)&sBl[r * 40 + c] = *(const uint4*)(bL + g);
        }
        __syncthreads();

#pragma unroll
        for (int ks = 0; ks < 32; ks += 16) {
            uint32_t ah[MI][4], al[MI][4], bh[4][2], bl[4][2];
#pragma unroll
            for (int mi = 0; mi < MI; mi++) {
                uint32_t off = (uint32_t)(((a_row + mi * 16) * 40 + ks + a_cofs) * 2);
                ldmatrix_x4(ah[mi][0], ah[mi][1], ah[mi][2], ah[mi][3], sAh_b + off);
                ldmatrix_x4(al[mi][0], al[mi][1], al[mi][2], al[mi][3], sAl_b + off);
            }
#pragma unroll
            for (int nj = 0; nj < 2; nj++) {
                uint32_t off = (uint32_t)(((b_row + nj * 16) * 40 + ks + b_cofs) * 2);
                ldmatrix_x4(bh[nj * 2][0], bh[nj * 2][1], bh[nj * 2 + 1][0], bh[nj * 2 + 1][1],
                            sBh_b + off);
                ldmatrix_x4(bl[nj * 2][0], bl[nj * 2][1], bl[nj * 2 + 1][0], bl[nj * 2 + 1][1],
                            sBl_b + off);
            }
#pragma unroll
            for (int mi = 0; mi < MI; mi++)
#pragma unroll
                for (int ni = 0; ni < 4; ni++) {
                    mma16816(acc[mi][ni], ah[mi], bh[ni]);
                    mma16816(acc[mi][ni], ah[mi], bl[ni]);
                    mma16816(acc[mi][ni], al[mi], bh[ni]);
                }
        }
        __syncthreads();
    }
}

// ============================ stage 1: projections ============================
__global__ __launch_bounds__(256)
void proj_mma_kernel(const float* __restrict__ bq1, const float* __restrict__ bk1,
                     const float* __restrict__ bv1, const float* __restrict__ bq2,
                     const float* __restrict__ bk2, const float* __restrict__ bv2)
{
    const int cb = blockIdx.x;
    const int bm = blockIdx.y * 128;
    const bf16 *bH, *bL;
    const float* bias;
    int r, bnl;
    if (cb < 32) {
        r = cb >> 3; bnl = (cb & 7) * 128;
        long long wo = (long long)r * 1048576 + (long long)bnl * 1024;
        bH = g_WTh + wo; bL = g_WTl + wo;
        bias = (r == 0) ? bq1 : (r == 1) ? bk1 : (r == 2) ? bq2 : bk2;
    } else {
        r = (cb - 32) >> 2; bnl = ((cb - 32) & 3) * 128;
        long long wo = 4194304LL + (long long)r * 524288 + (long long)bnl * 1024;
        bH = g_WTh + wo; bL = g_WTl + wo;
        bias = r ? bv2 : bv1;
    }
    float acc[4][4][4];
#pragma unroll
    for (int a = 0; a < 4; a++)
#pragma unroll
        for (int b = 0; b < 4; b++)
#pragma unroll
            for (int c = 0; c < 4; c++) acc[a][b][c] = 0.f;

    gemm_mma<128, 2, 4>(g_Xh + (long long)bm * 1024, g_Xl + (long long)bm * 1024, 1024,
                        bH, bL, 1024, 1024, acc);

    const int wid = threadIdx.x >> 5, lane = threadIdx.x & 31;
    const int g = lane >> 2, t = lane & 3;
    const int wm = (wid >> 2) * 64, wn = (wid & 3) * 32;
#pragma unroll
    for (int mi = 0; mi < 4; mi++) {
        int m0 = bm + wm + mi * 16 + g;
#pragma unroll
        for (int ni = 0; ni < 4; ni++) {
            int col = bnl + wn + ni * 8 + 2 * t;
            float b0 = bias[col], b1 = bias[col + 1];
            float v00 = acc[mi][ni][0] + b0, v01 = acc[mi][ni][1] + b1;
            float v10 = acc[mi][ni][2] + b0, v11 = acc[mi][ni][3] + b1;
            bf16 h00 = __float2bfloat16(v00), h01 = __float2bfloat16(v01);
            bf16 h10 = __float2bfloat16(v10), h11 = __float2bfloat16(v11);
            bf16 l00 = __float2bfloat16(v00 - __bfloat162float(h00));
            bf16 l01 = __float2bfloat16(v01 - __bfloat162float(h01));
            bf16 l10 = __float2bfloat16(v10 - __bfloat162float(h10));
            bf16 l11 = __float2bfloat16(v11 - __bfloat162float(h11));
            if (cb < 32) {
                long long o0 = (long long)m0 * 1024 + col;
                long long o1 = (long long)(m0 + 8) * 1024 + col;
                *(__nv_bfloat162*)&g_QKh[r][o0] = __nv_bfloat162(h00, h01);
                *(__nv_bfloat162*)&g_QKl[r][o0] = __nv_bfloat162(l00, l01);
                *(__nv_bfloat162*)&g_QKh[r][o1] = __nv_bfloat162(h10, h11);
                *(__nv_bfloat162*)&g_QKl[r][o1] = __nv_bfloat162(l10, l11);
            } else {
                int c0 = r * 512 + col, c1 = c0 + 1;
                g_VTh[(long long)c0 * 2048 + m0] = h00;
                g_VTh[(long long)c1 * 2048 + m0] = h01;
                g_VTh[(long long)c0 * 2048 + m0 + 8] = h10;
                g_VTh[(long long)c1 * 2048 + m0 + 8] = h11;
                g_VTl[(long long)c0 * 2048 + m0] = l00;
                g_VTl[(long long)c1 * 2048 + m0] = l01;
                g_VTl[(long long)c0 * 2048 + m0 + 8] = l10;
                g_VTl[(long long)c1 * 2048 + m0 + 8] = l11;
            }
        }
    }
}

// ============================ stage 2: scores ============================
__global__ __launch_bounds__(256)
void score_mma_kernel(float scale)
{
    const int z = blockIdx.z, mat = z >> 3, h = z & 7;
    const int bm = blockIdx.y * 128, bn = blockIdx.x * 128;
    const bf16* qh = g_QKh[mat * 2] + (long long)bm * 1024 + h * 128;
    const bf16* ql = g_QKl[mat * 2] + (long long)bm * 1024 + h * 128;
    const bf16* kh = g_QKh[mat * 2 + 1] + (long long)bn * 1024 + h * 128;
    const bf16* kl = g_QKl[mat * 2 + 1] + (long long)bn * 1024 + h * 128;

    float acc[4][4][4];
#pragma unroll
    for (int a = 0; a < 4; a++)
#pragma unroll
        for (int b = 0; b < 4; b++)
#pragma unroll
            for (int c = 0; c < 4; c++) acc[a][b][c] = 0.f;

    gemm_mma<128, 2, 4>(qh, ql, 1024, kh, kl, 1024, 128, acc);

    float* S = (mat ? g_S2 : g_S1) + (long long)h * N_TOK * N_TOK;
    const int wid = threadIdx.x >> 5, lane = threadIdx.x & 31;
    const int g = lane >> 2, t = lane & 3;
    const int wm = (wid >> 2) * 64, wn = (wid & 3) * 32;
#pragma unroll
    for (int mi = 0; mi < 4; mi++) {
        int m0 = bm + wm + mi * 16 + g;
#pragma unroll
        for (int ni = 0; ni < 4; ni++) {
            int n0 = bn + wn + ni * 8 + 2 * t;
            float2 r0 = make_float2(acc[mi][ni][0] * scale, acc[mi][ni][1] * scale);
            float2 r1 = make_float2(acc[mi][ni][2] * scale, acc[mi][ni][3] * scale);
            *(float2*)(S + (long long)m0 * N_TOK + n0) = r0;
            *(float2*)(S + (long long)(m0 + 8) * N_TOK + n0) = r1;
        }
    }
}

// ============================ stage 3: dual gathered softmax ============================
__device__ __forceinline__ float warpRedMax(float v) {
#pragma unroll
    for (int o = 16; o > 0; o >>= 1) v = fmaxf(v, __shfl_xor_sync(0xffffffffu, v, o));
    return v;
}
__device__ __forceinline__ float warpRedSum(float v) {
#pragma unroll
    for (int o = 16; o > 0; o >>= 1) v += __shfl_xor_sync(0xffffffffu, v, o);
    return v;
}

__global__ __launch_bounds__(256)
void softmax_gather_kernel(const int* __restrict__ n2c, const int* __restrict__ c2n)
{
    const int n = blockIdx.x;
    const int h = blockIdx.y;
    float* s1row = g_S1 + ((long long)h * N_TOK + n) * N_TOK;
    float* s2row = g_S2 + ((long long)h * N_TOK + n) * N_TOK;
    __shared__ float sh1[N_TOK];
    __shared__ float sh2[N_TOK];
    __shared__ float red[32];
    const int tid = threadIdx.x;
    const int lane = tid & 31, wid = tid >> 5;

#pragma unroll
    for (int i = 0; i < 8; i++) {
        int m = tid + i * 256;
        sh1[m] = s1row[m];
        sh2[m] = s2row[m];
    }
    __syncthreads();

    const int* c2nrow = c2n + (long long)n * N_TOK;
    const int* n2crow = n2c + (long long)n * N_TOK;
    const float* m1row = g_M1 + (long long)n * N_TOK;
    const float* m2row = g_M2 + (long long)n * N_TOK;

    float z1[8], z2[8];
    float mx1 = -1e30f, mx2 = -1e30f;
#pragma unroll
    for (int i = 0; i < 8; i++) {
        int m = tid + i * 256;
        z1[i] = sh1[m] + sh2[c2nrow[m]] + m1row[m];
        z2[i] = sh2[m] + sh1[n2crow[m]] + m2row[m];
        mx1 = fmaxf(mx1, z1[i]);
        mx2 = fmaxf(mx2, z2[i]);
    }
    mx1 = warpRedMax(mx1);
    mx2 = warpRedMax(mx2);
    if (lane == 0) { red[wid] = mx1; red[wid + 8] = mx2; }
    __syncthreads();
    if (wid == 0) {
        float a = (lane < 8) ? red[lane] : -1e30f;
        float b = (lane < 8) ? red[lane + 8] : -1e30f;
        a = warpRedMax(a);
        b = warpRedMax(b);
        if (lane == 0) { red[16] = a; red[17] = b; }
    }
    __syncthreads();
    mx1 = red[16];
    mx2 = red[17];

    float sum1 = 0.f, sum2 = 0.f;
#pragma unroll
    for (int i = 0; i < 8; i++) {
        z1[i] = __expf(z1[i] - mx1);
        z2[i] = __expf(z2[i] - mx2);
        sum1 += z1[i];
        sum2 += z2[i];
    }
    sum1 = warpRedSum(sum1);
    sum2 = warpRedSum(sum2);
    __syncthreads();
    if (lane == 0) { red[wid] = sum1; red[wid + 8] = sum2; }
    __syncthreads();
    if (wid == 0) {
        float a = (lane < 8) ? red[lane] : 0.f;
        float b = (lane < 8) ? red[lane + 8] : 0.f;
        a = warpRedSum(a);
        b = warpRedSum(b);
        if (lane == 0) { red[16] = a; red[17] = b; }
    }
    __syncthreads();
    float inv1 = 1.f / red[16];
    float inv2 = 1.f / red[17];
    // write attention rows in place as bf16 split: [hi x2048 | lo x2048]
    bf16* a1 = reinterpret_cast<bf16*>(s1row);
    bf16* a2 = reinterpret_cast<bf16*>(s2row);
#pragma unroll
    for (int i = 0; i < 8; i++) {
        int m = tid + i * 256;
        float p1 = z1[i] * inv1;
        float p2 = z2[i] * inv2;
        bf16 h1 = __float2bfloat16(p1);
        bf16 h2 = __float2bfloat16(p2);
        a1[m] = h1; a1[2048 + m] = __float2bfloat16(p1 - __bfloat162float(h1));
        a2[m] = h2; a2[2048 + m] = __float2bfloat16(p2 - __bfloat162float(h2));
    }
}

// ============================ stage 4: AV + concat ============================
__global__ __launch_bounds__(256)
void av_mma_kernel(float* __restrict__ out)
{
    const int z = blockIdx.z, mat = z >> 3, h = z & 7;
    const int bm = blockIdx.y * 128;
    const bf16* Ab = reinterpret_cast<const bf16*>(mat ? g_S2 : g_S1);
    const bf16* aH = Ab + ((long long)h * N_TOK + bm) * 4096;
    const bf16* aL = aH + 2048;
    const bf16* bH = g_VTh + (long long)(mat * 512 + h * 64) * 2048;
    const bf16* bL = g_VTl + (long long)(mat * 512 + h * 64) * 2048;

    float acc[2][4][4];
#pragma unroll
    for (int a = 0; a < 2; a++)
#pragma unroll
        for (int b = 0; b < 4; b++)
#pragma unroll
            for (int c = 0; c < 4; c++) acc[a][b][c] = 0.f;

    gemm_mma<64, 4, 2>(aH, aL, 4096, bH, bL, 2048, 2048, acc);

    const int wid = threadIdx.x >> 5, lane = threadIdx.x & 31;
    const int g = lane >> 2, t = lane & 3;
    const int wm = (wid >> 1) * 32, wn = (wid & 1) * 32;
    const int cbase = mat * 512 + h * 64;
#pragma unroll
    for (int mi = 0; mi < 2; mi++) {
        int m0 = bm + wm + mi * 16 + g;
#pragma unroll
        for (int ni = 0; ni < 4; ni++) {
            int col = cbase + wn + ni * 8 + 2 * t;
            *(float2*)(out + (long long)m0 * 1024 + col) =
                make_float2(acc[mi][ni][0], acc[mi][ni][1]);
            *(float2*)(out + (long long)(m0 + 8) * 1024 + col) =
                make_float2(acc[mi][ni][2], acc[mi][ni][3]);
        }
    }
}

// ============================ launch ============================
extern "C" void kernel_launch(void* const* d_in, const int* in_sizes, int n_in,
                              void* d_out, int out_size)
{
    const float* x   = (const float*)d_in[0];
    const float* fst = (const float*)d_in[1];
    const float* sec = (const float*)d_in[2];
    const int*   n2c = (const int*)d_in[3];
    const int*   c2n = (const int*)d_in[4];
    const float* Wq1 = (const float*)d_in[5];
    const float* bq1 = (const float*)d_in[6];
    const float* Wk1 = (const float*)d_in[7];
    const float* bk1 = (const float*)d_in[8];
    const float* Wv1 = (const float*)d_in[9];
    const float* bv1 = (const float*)d_in[10];
    const float* Wq2 = (const float*)d_in[11];
    const float* bq2 = (const float*)d_in[12];
    const float* Wk2 = (const float*)d_in[13];
    const float* bk2 = (const float*)d_in[14];
    const float* Wv2 = (const float*)d_in[15];
    const float* bv2 = (const float*)d_in[16];
    float* out = (float*)d_out;

    // stage 0: transposed masks + bf16 split conversions
    mask_transpose_kernel<<<dim3(64, 64), dim3(32, 8)>>>(fst, sec);
    convx_kernel<<<2048, 256>>>(x);
    convw_kernel<<<dim3(32, 32, 6), dim3(32, 8)>>>(Wq1, Wk1, Wq2, Wk2, Wv1, Wv2);

    // stage 1: projections (640 CTAs, mma.sync)
    proj_mma_kernel<<<dim3(40, 16), 256>>>(bq1, bk1, bv1, bq2, bk2, bv2);

    // stage 2: scores (4096 CTAs, mma.sync)
    const float scale = 0.08838834764831845f;  // 1/sqrt(128)
    score_mma_kernel<<<dim3(16, 16, 16), 256>>>(scale);

    // stage 3: gathered dual softmax -> bf16-split attention, in place
    softmax_gather_kernel<<<dim3(2048, 8), 256>>>(n2c, c2n);

    // stage 4: AV + concat (256 CTAs, mma.sync)
    av_mma_kernel<<<dim3(1, 16, 16), 256>>>(out);
}

// round 4
// speedup vs baseline: 2.2598x; 1.1133x over previous
#include <cuda_runtime.h>
#include <cuda_bf16.h>
#include <cstdint>

#define N_TOK 2048
#define NN (8LL * 2048 * 2048)

typedef __nv_bfloat16 bf16;

__device__ __forceinline__ uint32_t smem_to_u32(const void* p) {
    uint32_t a;
    asm("{ .reg .u64 t; cvta.to.shared.u64 t, %1; cvt.u32.u64 %0, t; }" : "=r"(a) : "l"(p));
    return a;
}

__device__ __forceinline__ void ldmatrix_x4(uint32_t& r0, uint32_t& r1, uint32_t& r2,
                                            uint32_t& r3, uint32_t addr) {
    asm volatile("ldmatrix.sync.aligned.m8n8.x4.shared.b16 {%0,%1,%2,%3}, [%4];"
                 : "=r"(r0), "=r"(r1), "=r"(r2), "=r"(r3) : "r"(addr));
}

__device__ __forceinline__ void mma16816(float c[4], const uint32_t a[4], const uint32_t b[2]) {
    asm volatile(
        "mma.sync.aligned.m16n8k16.row.col.f32.bf16.bf16.f32 "
        "{%0,%1,%2,%3}, {%4,%5,%6,%7}, {%8,%9}, {%0,%1,%2,%3};"
        : "+f"(c[0]), "+f"(c[1]), "+f"(c[2]), "+f"(c[3])
        : "r"(a[0]), "r"(a[1]), "r"(a[2]), "r"(a[3]), "r"(b[0]), "r"(b[1]));
}

#define CP_ASYNC_CG(smem_addr, gmem_ptr) \
    asm volatile("cp.async.cg.shared.global [%0], [%1], 16;" \
                 :: "r"(smem_addr), "l"(gmem_ptr))
#define CP_ASYNC_COMMIT() asm volatile("cp.async.commit_group;" ::: "memory")
#define CP_ASYNC_WAIT(n)  asm volatile("cp.async.wait_group %0;" :: "n"(n) : "memory")

// ============================ device scratch ============================
__device__ __align__(16) bf16 g_Xh[2048 * 1024];
__device__ __align__(16) bf16 g_Xl[2048 * 1024];
__device__ __align__(16) bf16 g_WTh[5242880];   // q1,k1,q2,k2 (1M each) + v1,v2 (512K each), [N,K]
__device__ __align__(16) bf16 g_WTl[5242880];
__device__ __align__(16) bf16 g_QKh[4][2048 * 1024];  // 0:q1 1:k1 2:q2 3:k2
__device__ __align__(16) bf16 g_QKl[4][2048 * 1024];
__device__ __align__(16) bf16 g_VTh[1024 * 2048];     // rows: mat*512 + vcol, cols: token
__device__ __align__(16) bf16 g_VTl[1024 * 2048];
__device__ __align__(16) float g_S1[NN];   // fp32 scores; after softmax: [hi bf16 x2048 | lo bf16 x2048] per row
__device__ __align__(16) float g_S2[NN];
__device__ float g_M1[2048LL * 2048];
__device__ float g_M2[2048LL * 2048];

// ============================ conversion kernels ============================
__global__ __launch_bounds__(256) void convx_kernel(const float* __restrict__ x) {
    int i = (blockIdx.x * 256 + threadIdx.x) * 4;
    float4 v = *(const float4*)(x + i);
    float vv[4] = {v.x, v.y, v.z, v.w};
    bf16 h[4], l[4];
#pragma unroll
    for (int j = 0; j < 4; j++) {
        h[j] = __float2bfloat16(vv[j]);
        l[j] = __float2bfloat16(vv[j] - __bfloat162float(h[j]));
    }
    *(uint2*)&g_Xh[i] = *(uint2*)h;
    *(uint2*)&g_Xl[i] = *(uint2*)l;
}

__global__ __launch_bounds__(256)
void convw_kernel(const float* __restrict__ w0, const float* __restrict__ w1,
                  const float* __restrict__ w2, const float* __restrict__ w3,
                  const float* __restrict__ w4, const float* __restrict__ w5) {
    int z = blockIdx.z;
    const float* W;
    int Ncols;
    long long base;
    switch (z) {
        case 0: W = w0; Ncols = 1024; base = 0; break;
        case 1: W = w1; Ncols = 1024; base = 1048576; break;
        case 2: W = w2; Ncols = 1024; base = 2097152; break;
        case 3: W = w3; Ncols = 1024; base = 3145728; break;
        case 4: W = w4; Ncols = 512;  base = 4194304; break;
        default:W = w5; Ncols = 512;  base = 4718592; break;
    }
    int bn = blockIdx.x * 32, bk = blockIdx.y * 32;
    if (bn >= Ncols) return;
    __shared__ float t[32][33];
#pragma unroll
    for (int i = threadIdx.y; i < 32; i += 8)
        t[i][threadIdx.x] = W[(long long)(bk + i) * Ncols + bn + threadIdx.x];
    __syncthreads();
#pragma unroll
    for (int i = threadIdx.y; i < 32; i += 8) {
        float v = t[threadIdx.x][i];
        bf16 hh = __float2bfloat16(v);
        long long o = base + (long long)(bn + i) * 1024 + bk + threadIdx.x;
        g_WTh[o] = hh;
        g_WTl[o] = __float2bfloat16(v - __bfloat162float(hh));
    }
}

__global__ void mask_transpose_kernel(const float* __restrict__ G1,
                                      const float* __restrict__ G2) {
    __shared__ float t1[32][33];
    __shared__ float t2[32][33];
    int bx = blockIdx.x * 32;
    int by = blockIdx.y * 32;
    int x = bx + threadIdx.x;
#pragma unroll
    for (int i = threadIdx.y; i < 32; i += 8) {
        t1[i][threadIdx.x] = G1[(long long)(by + i) * N_TOK + x];
        t2[i][threadIdx.x] = G2[(long long)(by + i) * N_TOK + x];
    }
    __syncthreads();
    int ox = by + threadIdx.x;
#pragma unroll
    for (int i = threadIdx.y; i < 32; i += 8) {
        g_M1[(long long)(bx + i) * N_TOK + ox] = (t1[threadIdx.x][i] - 1.f) * 10000.f;
        g_M2[(long long)(bx + i) * N_TOK + ox] = (t2[threadIdx.x][i] - 1.f) * 10000.f;
    }
}

// ============================ pipelined mma.sync GEMM body ============================
// acc[MI][4][4] += A(128,K) * B(BN,K)^T in 3-term bf16 split.
// 2-stage cp.async double buffer in dynamic smem. Rows padded to 40 bf16 (80B).
// Stage layout (bytes): [Ah 10240 | Al 10240 | Bh BN*80 | Bl BN*80]
template <int BN, int WM, int WN>
__device__ __forceinline__ void gemm_mma(
    const bf16* __restrict__ aH, const bf16* __restrict__ aL, int lda,
    const bf16* __restrict__ bH, const bf16* __restrict__ bL, int ldb,
    int K, float acc[128 / (WM * 16)][4][4])
{
    constexpr int MI = 128 / (WM * 16);
    constexpr int OFF_AL = 10240;
    constexpr int OFF_BH = 20480;
    constexpr int OFF_BL = 20480 + BN * 80;
    constexpr int STG = 20480 + BN * 160;
    extern __shared__ __align__(16) char sm[];
    const uint32_t smb = smem_to_u32(sm);
    const int tid = threadIdx.x;
    const int wid = tid >> 5, lane = tid & 31;
    const int wm = (wid / WN) * (MI * 16);
    const int wn = (wid % WN) * 32;
    const int a_row = wm + (lane & 7) + ((lane >> 3) & 1) * 8;
    const int a_cofs = (lane >> 4) * 8;
    const int b_row = wn + (lane & 7) + ((lane >> 4) & 1) * 8;
    const int b_cofs = ((lane >> 3) & 1) * 8;

    const int r_cp = tid >> 2;          // 0..63
    const int c_cp = (tid & 3) * 8;     // 0,8,16,24
    const int NC = K >> 5;

    auto issue_stage = [&](int ic) {
        const uint32_t sb = smb + (uint32_t)(ic & 1) * STG;
        const int k0 = ic * 32;
#pragma unroll
        for (int i = 0; i < 2; i++) {
            int r = r_cp + i * 64;
            uint32_t so = (uint32_t)(r * 80 + c_cp * 2);
            CP_ASYNC_CG(sb + so, aH + r * lda + k0 + c_cp);
            CP_ASYNC_CG(sb + OFF_AL + so, aL + r * lda + k0 + c_cp);
        }
#pragma unroll
        for (int i = 0; i < BN / 64; i++) {
            int r = r_cp + i * 64;
            uint32_t so = (uint32_t)(r * 80 + c_cp * 2);
            CP_ASYNC_CG(sb + OFF_BH + so, bH + r * ldb + k0 + c_cp);
            CP_ASYNC_CG(sb + OFF_BL + so, bL + r * ldb + k0 + c_cp);
        }
        CP_ASYNC_COMMIT();
    };

    issue_stage(0);
    for (int ic = 0; ic < NC; ic++) {
        if (ic + 1 < NC) { issue_stage(ic + 1); CP_ASYNC_WAIT(1); }
        else             { CP_ASYNC_WAIT(0); }
        __syncthreads();
        const uint32_t sb = smb + (uint32_t)(ic & 1) * STG;
#pragma unroll
        for (int ks = 0; ks < 32; ks += 16) {
            uint32_t ah[MI][4], al[MI][4], bh[4][2], bl[4][2];
#pragma unroll
            for (int mi = 0; mi < MI; mi++) {
                uint32_t off = (uint32_t)(((a_row + mi * 16) * 40 + ks + a_cofs) * 2);
                ldmatrix_x4(ah[mi][0], ah[mi][1], ah[mi][2], ah[mi][3], sb + off);
                ldmatrix_x4(al[mi][0], al[mi][1], al[mi][2], al[mi][3], sb + OFF_AL + off);
            }
#pragma unroll
            for (int nj = 0; nj < 2; nj++) {
                uint32_t off = (uint32_t)(((b_row + nj * 16) * 40 + ks + b_cofs) * 2);
                ldmatrix_x4(bh[nj * 2][0], bh[nj * 2][1], bh[nj * 2 + 1][0], bh[nj * 2 + 1][1],
                            sb + OFF_BH + off);
                ldmatrix_x4(bl[nj * 2][0], bl[nj * 2][1], bl[nj * 2 + 1][0], bl[nj * 2 + 1][1],
                            sb + OFF_BL + off);
            }
#pragma unroll
            for (int mi = 0; mi < MI; mi++)
#pragma unroll
                for (int ni = 0; ni < 4; ni++) {
                    mma16816(acc[mi][ni], ah[mi], bh[ni]);
                    mma16816(acc[mi][ni], ah[mi], bl[ni]);
                    mma16816(acc[mi][ni], al[mi], bh[ni]);
                }
        }
        __syncthreads();
    }
}

// ============================ stage 1: projections ============================
__global__ __launch_bounds__(256, 2)
void proj_mma_kernel(const float* __restrict__ bq1, const float* __restrict__ bk1,
                     const float* __restrict__ bv1, const float* __restrict__ bq2,
                     const float* __restrict__ bk2, const float* __restrict__ bv2)
{
    const int cb = blockIdx.x;
    const int bm = blockIdx.y * 128;
    const bf16 *bH, *bL;
    const float* bias;
    int r, bnl;
    if (cb < 32) {
        r = cb >> 3; bnl = (cb & 7) * 128;
        long long wo = (long long)r * 1048576 + (long long)bnl * 1024;
        bH = g_WTh + wo; bL = g_WTl + wo;
        bias = (r == 0) ? bq1 : (r == 1) ? bk1 : (r == 2) ? bq2 : bk2;
    } else {
        r = (cb - 32) >> 2; bnl = ((cb - 32) & 3) * 128;
        long long wo = 4194304LL + (long long)r * 524288 + (long long)bnl * 1024;
        bH = g_WTh + wo; bL = g_WTl + wo;
        bias = r ? bv2 : bv1;
    }
    float acc[4][4][4];
#pragma unroll
    for (int a = 0; a < 4; a++)
#pragma unroll
        for (int b = 0; b < 4; b++)
#pragma unroll
            for (int c = 0; c < 4; c++) acc[a][b][c] = 0.f;

    gemm_mma<128, 2, 4>(g_Xh + (long long)bm * 1024, g_Xl + (long long)bm * 1024, 1024,
                        bH, bL, 1024, 1024, acc);

    const int wid = threadIdx.x >> 5, lane = threadIdx.x & 31;
    const int g = lane >> 2, t = lane & 3;
    const int wm = (wid >> 2) * 64, wn = (wid & 3) * 32;
#pragma unroll
    for (int mi = 0; mi < 4; mi++) {
        int m0 = bm + wm + mi * 16 + g;
#pragma unroll
        for (int ni = 0; ni < 4; ni++) {
            int col = bnl + wn + ni * 8 + 2 * t;
            float b0 = bias[col], b1 = bias[col + 1];
            float v00 = acc[mi][ni][0] + b0, v01 = acc[mi][ni][1] + b1;
            float v10 = acc[mi][ni][2] + b0, v11 = acc[mi][ni][3] + b1;
            bf16 h00 = __float2bfloat16(v00), h01 = __float2bfloat16(v01);
            bf16 h10 = __float2bfloat16(v10), h11 = __float2bfloat16(v11);
            bf16 l00 = __float2bfloat16(v00 - __bfloat162float(h00));
            bf16 l01 = __float2bfloat16(v01 - __bfloat162float(h01));
            bf16 l10 = __float2bfloat16(v10 - __bfloat162float(h10));
            bf16 l11 = __float2bfloat16(v11 - __bfloat162float(h11));
            if (cb < 32) {
                long long o0 = (long long)m0 * 1024 + col;
                long long o1 = (long long)(m0 + 8) * 1024 + col;
                *(__nv_bfloat162*)&g_QKh[r][o0] = __nv_bfloat162(h00, h01);
                *(__nv_bfloat162*)&g_QKl[r][o0] = __nv_bfloat162(l00, l01);
                *(__nv_bfloat162*)&g_QKh[r][o1] = __nv_bfloat162(h10, h11);
                *(__nv_bfloat162*)&g_QKl[r][o1] = __nv_bfloat162(l10, l11);
            } else {
                int c0 = r * 512 + col, c1 = c0 + 1;
                g_VTh[(long long)c0 * 2048 + m0] = h00;
                g_VTh[(long long)c1 * 2048 + m0] = h01;
                g_VTh[(long long)c0 * 2048 + m0 + 8] = h10;
                g_VTh[(long long)c1 * 2048 + m0 + 8] = h11;
                g_VTl[(long long)c0 * 2048 + m0] = l00;
                g_VTl[(long long)c1 * 2048 + m0] = l01;
                g_VTl[(long long)c0 * 2048 + m0 + 8] = l10;
                g_VTl[(long long)c1 * 2048 + m0 + 8] = l11;
            }
        }
    }
}

// ============================ stage 2: scores ============================
__global__ __launch_bounds__(256, 2)
void score_mma_kernel(float scale)
{
    const int z = blockIdx.z, mat = z >> 3, h = z & 7;
    const int bm = blockIdx.y * 128, bn = blockIdx.x * 128;
    const bf16* qh = g_QKh[mat * 2] + (long long)bm * 1024 + h * 128;
    const bf16* ql = g_QKl[mat * 2] + (long long)bm * 1024 + h * 128;
    const bf16* kh = g_QKh[mat * 2 + 1] + (long long)bn * 1024 + h * 128;
    const bf16* kl = g_QKl[mat * 2 + 1] + (long long)bn * 1024 + h * 128;

    float acc[4][4][4];
#pragma unroll
    for (int a = 0; a < 4; a++)
#pragma unroll
        for (int b = 0; b < 4; b++)
#pragma unroll
            for (int c = 0; c < 4; c++) acc[a][b][c] = 0.f;

    gemm_mma<128, 2, 4>(qh, ql, 1024, kh, kl, 1024, 128, acc);

    float* S = (mat ? g_S2 : g_S1) + (long long)h * N_TOK * N_TOK;
    const int wid = threadIdx.x >> 5, lane = threadIdx.x & 31;
    const int g = lane >> 2, t = lane & 3;
    const int wm = (wid >> 2) * 64, wn = (wid & 3) * 32;
#pragma unroll
    for (int mi = 0; mi < 4; mi++) {
        int m0 = bm + wm + mi * 16 + g;
#pragma unroll
        for (int ni = 0; ni < 4; ni++) {
            int n0 = bn + wn + ni * 8 + 2 * t;
            float2 r0 = make_float2(acc[mi][ni][0] * scale, acc[mi][ni][1] * scale);
            float2 r1 = make_float2(acc[mi][ni][2] * scale, acc[mi][ni][3] * scale);
            *(float2*)(S + (long long)m0 * N_TOK + n0) = r0;
            *(float2*)(S + (long long)(m0 + 8) * N_TOK + n0) = r1;
        }
    }
}

// ============================ stage 3: dual gathered softmax ============================
__device__ __forceinline__ float warpRedMax(float v) {
#pragma unroll
    for (int o = 16; o > 0; o >>= 1) v = fmaxf(v, __shfl_xor_sync(0xffffffffu, v, o));
    return v;
}
__device__ __forceinline__ float warpRedSum(float v) {
#pragma unroll
    for (int o = 16; o > 0; o >>= 1) v += __shfl_xor_sync(0xffffffffu, v, o);
    return v;
}

__global__ __launch_bounds__(256)
void softmax_gather_kernel(const int* __restrict__ n2c, const int* __restrict__ c2n)
{
    const int n = blockIdx.x;
    const int h = blockIdx.y;
    float* s1row = g_S1 + ((long long)h * N_TOK + n) * N_TOK;
    float* s2row = g_S2 + ((long long)h * N_TOK + n) * N_TOK;
    __shared__ float sh1[N_TOK];
    __shared__ float sh2[N_TOK];
    __shared__ float red[32];
    const int tid = threadIdx.x;
    const int lane = tid & 31, wid = tid >> 5;

#pragma unroll
    for (int i = 0; i < 8; i++) {
        int m = tid + i * 256;
        sh1[m] = s1row[m];
        sh2[m] = s2row[m];
    }
    __syncthreads();

    const int* c2nrow = c2n + (long long)n * N_TOK;
    const int* n2crow = n2c + (long long)n * N_TOK;
    const float* m1row = g_M1 + (long long)n * N_TOK;
    const float* m2row = g_M2 + (long long)n * N_TOK;

    float z1[8], z2[8];
    float mx1 = -1e30f, mx2 = -1e30f;
#pragma unroll
    for (int i = 0; i < 8; i++) {
        int m = tid + i * 256;
        z1[i] = sh1[m] + sh2[c2nrow[m]] + m1row[m];
        z2[i] = sh2[m] + sh1[n2crow[m]] + m2row[m];
        mx1 = fmaxf(mx1, z1[i]);
        mx2 = fmaxf(mx2, z2[i]);
    }
    mx1 = warpRedMax(mx1);
    mx2 = warpRedMax(mx2);
    if (lane == 0) { red[wid] = mx1; red[wid + 8] = mx2; }
    __syncthreads();
    if (wid == 0) {
        float a = (lane < 8) ? red[lane] : -1e30f;
        float b = (lane < 8) ? red[lane + 8] : -1e30f;
        a = warpRedMax(a);
        b = warpRedMax(b);
        if (lane == 0) { red[16] = a; red[17] = b; }
    }
    __syncthreads();
    mx1 = red[16];
    mx2 = red[17];

    float sum1 = 0.f, sum2 = 0.f;
#pragma unroll
    for (int i = 0; i < 8; i++) {
        z1[i] = __expf(z1[i] - mx1);
        z2[i] = __expf(z2[i] - mx2);
        sum1 += z1[i];
        sum2 += z2[i];
    }
    sum1 = warpRedSum(sum1);
    sum2 = warpRedSum(sum2);
    __syncthreads();
    if (lane == 0) { red[wid] = sum1; red[wid + 8] = sum2; }
    __syncthreads();
    if (wid == 0) {
        float a = (lane < 8) ? red[lane] : 0.f;
        float b = (lane < 8) ? red[lane + 8] : 0.f;
        a = warpRedSum(a);
        b = warpRedSum(b);
        if (lane == 0) { red[16] = a; red[17] = b; }
    }
    __syncthreads();
    float inv1 = 1.f / red[16];
    float inv2 = 1.f / red[17];
    bf16* a1 = reinterpret_cast<bf16*>(s1row);
    bf16* a2 = reinterpret_cast<bf16*>(s2row);
#pragma unroll
    for (int i = 0; i < 8; i++) {
        int m = tid + i * 256;
        float p1 = z1[i] * inv1;
        float p2 = z2[i] * inv2;
        bf16 h1 = __float2bfloat16(p1);
        bf16 h2 = __float2bfloat16(p2);
        a1[m] = h1; a1[2048 + m] = __float2bfloat16(p1 - __bfloat162float(h1));
        a2[m] = h2; a2[2048 + m] = __float2bfloat16(p2 - __bfloat162float(h2));
    }
}

// ============================ stage 4: AV + concat ============================
__global__ __launch_bounds__(256, 2)
void av_mma_kernel(float* __restrict__ out)
{
    const int z = blockIdx.z, mat = z >> 3, h = z & 7;
    const int bm = blockIdx.y * 128;
    const bf16* Ab = reinterpret_cast<const bf16*>(mat ? g_S2 : g_S1);
    const bf16* aH = Ab + ((long long)h * N_TOK + bm) * 4096;
    const bf16* aL = aH + 2048;
    const bf16* bH = g_VTh + (long long)(mat * 512 + h * 64) * 2048;
    const bf16* bL = g_VTl + (long long)(mat * 512 + h * 64) * 2048;

    float acc[2][4][4];
#pragma unroll
    for (int a = 0; a < 2; a++)
#pragma unroll
        for (int b = 0; b < 4; b++)
#pragma unroll
            for (int c = 0; c < 4; c++) acc[a][b][c] = 0.f;

    gemm_mma<64, 4, 2>(aH, aL, 4096, bH, bL, 2048, 2048, acc);

    const int wid = threadIdx.x >> 5, lane = threadIdx.x & 31;
    const int g = lane >> 2, t = lane & 3;
    const int wm = (wid >> 1) * 32, wn = (wid & 1) * 32;
    const int cbase = mat * 512 + h * 64;
#pragma unroll
    for (int mi = 0; mi < 2; mi++) {
        int m0 = bm + wm + mi * 16 + g;
#pragma unroll
        for (int ni = 0; ni < 4; ni++) {
            int col = cbase + wn + ni * 8 + 2 * t;
            *(float2*)(out + (long long)m0 * 1024 + col) =
                make_float2(acc[mi][ni][0], acc[mi][ni][1]);
            *(float2*)(out + (long long)(m0 + 8) * 1024 + col) =
                make_float2(acc[mi][ni][2], acc[mi][ni][3]);
        }
    }
}

// ============================ launch ============================
extern "C" void kernel_launch(void* const* d_in, const int* in_sizes, int n_in,
                              void* d_out, int out_size)
{
    const float* x   = (const float*)d_in[0];
    const float* fst = (const float*)d_in[1];
    const float* sec = (const float*)d_in[2];
    const int*   n2c = (const int*)d_in[3];
    const int*   c2n = (const int*)d_in[4];
    const float* Wq1 = (const float*)d_in[5];
    const float* bq1 = (const float*)d_in[6];
    const float* Wk1 = (const float*)d_in[7];
    const float* bk1 = (const float*)d_in[8];
    const float* Wv1 = (const float*)d_in[9];
    const float* bv1 = (const float*)d_in[10];
    const float* Wq2 = (const float*)d_in[11];
    const float* bq2 = (const float*)d_in[12];
    const float* Wk2 = (const float*)d_in[13];
    const float* bk2 = (const float*)d_in[14];
    const float* Wv2 = (const float*)d_in[15];
    const float* bv2 = (const float*)d_in[16];
    float* out = (float*)d_out;

    static bool attr_set = false;
    if (!attr_set) {
        cudaFuncSetAttribute(proj_mma_kernel, cudaFuncAttributeMaxDynamicSharedMemorySize, 81920);
        cudaFuncSetAttribute(score_mma_kernel, cudaFuncAttributeMaxDynamicSharedMemorySize, 81920);
        cudaFuncSetAttribute(av_mma_kernel, cudaFuncAttributeMaxDynamicSharedMemorySize, 61440);
        attr_set = true;
    }

    // stage 0: transposed masks + bf16 split conversions
    mask_transpose_kernel<<<dim3(64, 64), dim3(32, 8)>>>(fst, sec);
    convx_kernel<<<2048, 256>>>(x);
    convw_kernel<<<dim3(32, 32, 6), dim3(32, 8)>>>(Wq1, Wk1, Wq2, Wk2, Wv1, Wv2);

    // stage 1: projections (640 CTAs, pipelined mma.sync)
    proj_mma_kernel<<<dim3(40, 16), 256, 81920>>>(bq1, bk1, bv1, bq2, bk2, bv2);

    // stage 2: scores (4096 CTAs)
    const float scale = 0.08838834764831845f;  // 1/sqrt(128)
    score_mma_kernel<<<dim3(16, 16, 16), 256, 81920>>>(scale);

    // stage 3: gathered dual softmax -> bf16-split attention, in place
    softmax_gather_kernel<<<dim3(2048, 8), 256>>>(n2c, c2n);

    // stage 4: AV + concat (256 CTAs)
    av_mma_kernel<<<dim3(1, 16, 16), 256, 61440>>>(out);
}